// round 11
// baseline (speedup 1.0000x reference)
#include <cuda_runtime.h>
#include <cuda_fp16.h>
#include <stdint.h>
#include <math.h>

#define NTOK   4096
#define DMODEL 1024
#define DFF    4096
#define NEXP   8
#define NEXPX  9
#define NASSIGN (NTOK*2)
#define NROWS  (NASSIGN + NTOK)
#define SCALE_F 0.894427190999915878f

// ---------------- device scratch ----------------------------------------------------
__device__ __half d_W1x[(size_t)NEXPX * DFF * DMODEL];
__device__ __half d_W2x[(size_t)NEXPX * DMODEL * DFF];
__device__ float  d_b1x[NEXPX * DFF];
__device__ float  d_b2x[NEXPX * DMODEL];
__device__ __half d_xh[(size_t)NTOK * DMODEL];
__device__ __half d_Hh[(size_t)NROWS * DFF];
__device__ float  d_gates[NASSIGN];
__device__ int    d_assign_e[NASSIGN];
__device__ int    d_offsets[NEXPX + 1];
__device__ int    d_rows_token[NROWS];
__device__ float  d_growsc[NROWS];

// ---------------- helpers --------------------------------------------------------------
__device__ __forceinline__ float gelu_tanh(float v) {
    const float c0 = 0.7978845608028654f;
    const float c1 = 0.044715f;
    float t = tanhf(c0 * (v + c1 * v * v * v));
    return 0.5f * v * (1.0f + t);
}

__device__ __forceinline__ void mma16816(float* c, const uint32_t* a, const uint32_t* b) {
    asm volatile(
        "mma.sync.aligned.m16n8k16.row.col.f32.f16.f16.f32 "
        "{%0,%1,%2,%3}, {%4,%5,%6,%7}, {%8,%9}, {%0,%1,%2,%3};"
        : "+f"(c[0]), "+f"(c[1]), "+f"(c[2]), "+f"(c[3])
        : "r"(a[0]), "r"(a[1]), "r"(a[2]), "r"(a[3]), "r"(b[0]), "r"(b[1]));
}

__device__ __forceinline__ void ldsm4(uint32_t* r, uint32_t addr) {
    asm volatile("ldmatrix.sync.aligned.m8n8.x4.shared.b16 {%0,%1,%2,%3}, [%4];"
                 : "=r"(r[0]), "=r"(r[1]), "=r"(r[2]), "=r"(r[3]) : "r"(addr));
}

__device__ __forceinline__ uint32_t smem_u32(const void* p) {
    uint32_t a;
    asm("{ .reg .u64 t; cvta.to.shared.u64 t, %1; cvt.u32.u64 %0, t; }" : "=r"(a) : "l"(p));
    return a;
}

__device__ __forceinline__ void cp16(uint32_t saddr, const void* g, int srcsz) {
    asm volatile("cp.async.cg.shared.global [%0], [%1], 16, %2;"
                 :: "r"(saddr), "l"(g), "r"(srcsz) : "memory");
}
#define CP_COMMIT() asm volatile("cp.async.commit_group;" ::: "memory")
#define CP_WAIT1()  asm volatile("cp.async.wait_group 1;" ::: "memory")

__device__ __forceinline__ void cvt_store(const float4* __restrict__ src, uint2* __restrict__ dst, int i) {
    float4 v = src[i];
    __half2 a = __floats2half2_rn(v.x, v.y);
    __half2 b = __floats2half2_rn(v.z, v.w);
    dst[i] = make_uint2(*(uint32_t*)&a, *(uint32_t*)&b);
}

// ---------------- launch 1: router + W1/x/bias conversion (fused) -------------------------
#define CVT_BLOCKS 4096
__global__ void router_cvt(const float* __restrict__ x,
                           const float* __restrict__ wr,
                           const float4* __restrict__ W1, const float4* __restrict__ Ws1,
                           const float* __restrict__ b1, const float* __restrict__ bs1,
                           const float* __restrict__ b2, const float* __restrict__ bs2,
                           uint2* __restrict__ W1x, uint2* __restrict__ xh,
                           float* __restrict__ b1x, float* __restrict__ b2x) {
    if (blockIdx.x >= NTOK) {
        int idx0 = (blockIdx.x - NTOK) * blockDim.x + threadIdx.x;
        const int nthr = CVT_BLOCKS * 256;
        const int n4r = NEXP * DFF * DMODEL / 4;
        const int n4t = NEXPX * DFF * DMODEL / 4;
        for (int i = idx0; i < n4t; i += nthr) {
            float4 v = (i < n4r) ? W1[i] : Ws1[i - n4r];
            __half2 a = __floats2half2_rn(v.x, v.y);
            __half2 b = __floats2half2_rn(v.z, v.w);
            W1x[i] = make_uint2(*(uint32_t*)&a, *(uint32_t*)&b);
        }
        for (int i = idx0; i < NTOK * DMODEL / 4; i += nthr)
            cvt_store((const float4*)x, xh, i);
        for (int i = idx0; i < NEXPX * DFF; i += nthr)
            b1x[i] = (i < NEXP * DFF) ? b1[i] : bs1[i - NEXP * DFF];
        for (int i = idx0; i < NEXPX * DMODEL; i += nthr)
            b2x[i] = (i < NEXP * DMODEL) ? b2[i] : bs2[i - NEXP * DMODEL];
        return;
    }
    int t = blockIdx.x;
    int warp = threadIdx.x >> 5;
    int lane = threadIdx.x & 31;
    const float* xr = x + (size_t)t * DMODEL;
    const float* w  = wr + (size_t)warp * DMODEL;
    float s = 0.f;
    #pragma unroll 4
    for (int i = lane; i < DMODEL; i += 32) s += xr[i] * w[i];
    #pragma unroll
    for (int o = 16; o > 0; o >>= 1) s += __shfl_xor_sync(0xFFFFFFFFu, s, o);

    __shared__ float logits[NEXP];
    if (warp < NEXP && lane == 0) logits[warp] = s;
    __syncthreads();

    if (threadIdx.x == 0) {
        float mx = logits[0];
        #pragma unroll
        for (int e = 1; e < NEXP; e++) mx = fmaxf(mx, logits[e]);
        float p[NEXP]; float sum = 0.f;
        #pragma unroll
        for (int e = 0; e < NEXP; e++) { p[e] = expf(logits[e] - mx); sum += p[e]; }
        float inv = 1.f / sum;
        #pragma unroll
        for (int e = 0; e < NEXP; e++) p[e] *= inv;
        int i0 = 0;
        #pragma unroll
        for (int e = 1; e < NEXP; e++) if (p[e] > p[i0]) i0 = e;
        int i1 = -1;
        #pragma unroll
        for (int e = 0; e < NEXP; e++) {
            if (e == i0) continue;
            if (i1 < 0 || p[e] > p[i1]) i1 = e;
        }
        d_gates[2 * t + 0] = p[i0];
        d_gates[2 * t + 1] = p[i1];
        d_assign_e[2 * t + 0] = i0;
        d_assign_e[2 * t + 1] = i1;
    }
}

// ---------------- launch 2: single-block count + scan + place ----------------------------
__global__ void scanplace_kernel() {
    __shared__ int scount[NEXP];
    __shared__ int scursor[NEXP];
    int tid = threadIdx.x;
    if (tid < NEXP) scount[tid] = 0;
    __syncthreads();
    for (int a = tid; a < NASSIGN; a += blockDim.x)
        atomicAdd(&scount[d_assign_e[a]], 1);
    __syncthreads();
    if (tid == 0) {
        int s = 0;
        for (int e = 0; e < NEXP; e++) { d_offsets[e] = s; scursor[e] = s; s += scount[e]; }
        d_offsets[NEXP]  = s;
        d_offsets[NEXPX] = NROWS;
    }
    __syncthreads();
    for (int a = tid; a < NASSIGN; a += blockDim.x) {
        int e = d_assign_e[a];
        int r = atomicAdd(&scursor[e], 1);
        d_rows_token[r] = a >> 1;
        d_growsc[r] = SCALE_F * d_gates[a];
    }
    for (int t = tid; t < NTOK; t += blockDim.x) {
        d_rows_token[NASSIGN + t] = t;
        d_growsc[NASSIGN + t] = SCALE_F;
    }
}

// ================= fp16 HMMA grouped GEMM, 512 thr, cp.async 3-stage, BK=64 ==============
// 128x128x64 CTA tile, 512 thr (16 warps 4x4 -> 32x32 warp tiles), m16n8k16.
// acc 32 regs/thread -> target <=64 regs, 2 CTAs/SM, 32 warps/SM.
#define RS      144
#define T_B     18432
#define STAGE_B 36864
#define NSTAGE  3
#define GEMM_SMEM (NSTAGE * STAGE_B)
#define GTHREADS 512

__global__ __launch_bounds__(GTHREADS, 2)
void gemm_tc(const __half* __restrict__ Ah, int lda, const int* __restrict__ gather,
             const __half* __restrict__ Bh_base, size_t wstride,
             const float* __restrict__ bias_base, size_t bstride,
             __half* __restrict__ Ch, int ldc,
             float* __restrict__ out_at,
             const int* __restrict__ rows_token, const float* __restrict__ growsc,
             const int* __restrict__ offs, int K, int kh_count, int do_gelu,
             const float4* __restrict__ cw8, const float4* __restrict__ cws,
             uint2* __restrict__ cdst, int cn4r, int cn4t)
{
    extern __shared__ char smem[];
    int z = blockIdx.z;
    int nz_gemm = NEXPX * kh_count;
    if (z >= nz_gemm) {
        int idx0 = (blockIdx.y * gridDim.x + blockIdx.x) * blockDim.x + threadIdx.x;
        int nthr = gridDim.x * gridDim.y * blockDim.x;
        for (int i = idx0; i < cn4t; i += nthr) {
            float4 v = (i < cn4r) ? cw8[i] : cws[i - cn4r];
            __half2 a = __floats2half2_rn(v.x, v.y);
            __half2 b = __floats2half2_rn(v.z, v.w);
            cdst[i] = make_uint2(*(uint32_t*)&a, *(uint32_t*)&b);
        }
        return;
    }
    int e  = z / kh_count;
    int kh = z - e * kh_count;
    int Ks = K / kh_count;
    int lo = offs[e];
    int hi = offs[e + 1];
    int m0 = lo + blockIdx.y * 128;
    if (m0 >= hi) return;
    int n0 = blockIdx.x * 128;
    const __half* Bh = Bh_base + (size_t)e * wstride + kh * Ks;
    const float* bias = bias_base + (size_t)e * bstride;

    uint32_t sbase = smem_u32(smem);
    int tid  = threadIdx.x;
    int wid  = tid >> 5;
    int lane = tid & 31;
    int tig  = lane & 3;
    int wm   = wid >> 2;        // 0..3
    int wn   = wid & 3;         // 0..3

    // ---- cp.async coords: 512 threads cover A(128x128B) + B(128x128B), 64B each ------
    int r    = (tid >> 2) & 127;        // row 0..127
    int half = tid & 1;                 // 0/1 -> byte 0/64
    int isB  = (tid >> 1) & 1;          // 0=A, 1=B
    int cb   = half * 64;
    int arow = m0 + r;
    int av16 = (!isB && arow < hi) ? 16 : (isB ? 16 : 0);
    const char* gsrc;
    if (isB) {
        gsrc = (const char*)(Bh + (size_t)(n0 + r) * K) + cb;
    } else {
        int asrc = (arow < hi) ? (gather ? gather[arow] : arow) : 0;
        gsrc = (const char*)(Ah + (size_t)asrc * lda + kh * Ks) + cb;
    }
    uint32_t sdst = sbase + (uint32_t)(isB * T_B + r * RS + cb);

    // ---- ldmatrix lane offsets ----------------------------------------------------------
    uint32_t aoff[2], boff[4];
    #pragma unroll
    for (int mi = 0; mi < 2; mi++)
        aoff[mi] = (uint32_t)((wm * 32 + mi * 16 + (lane & 15)) * RS + (lane >> 4) * 16);
    #pragma unroll
    for (int ni = 0; ni < 4; ni++)
        boff[ni] = (uint32_t)(T_B + (wn * 32 + ni * 8 + (lane & 7)) * RS + (lane >> 3) * 16);

    float acc[2][4][4];
    #pragma unroll
    for (int mi = 0; mi < 2; mi++)
        #pragma unroll
        for (int ni = 0; ni < 4; ni++)
            #pragma unroll
            for (int q = 0; q < 4; q++) acc[mi][ni][q] = 0.f;

    int nk = Ks >> 6;

    auto issue = [&](int kt, int s) {
        uint32_t so = (uint32_t)(s * STAGE_B);
        int kbyte = kt << 7;
        #pragma unroll
        for (int j = 0; j < 4; j++)
            cp16(sdst + so + j * 16, gsrc + kbyte + j * 16, av16);
        CP_COMMIT();
    };

    issue(0, 0);
    if (nk > 1) issue(1, 1); else CP_COMMIT();

    int s = 0;
    for (int kt = 0; kt < nk; kt++) {
        CP_WAIT1();
        __syncthreads();

        if (kt + 2 < nk) issue(kt + 2, (s + 2) % NSTAGE);
        else CP_COMMIT();

        uint32_t st = sbase + (uint32_t)(s * STAGE_B);

        uint32_t bhf[4][4];
        #pragma unroll
        for (int ks = 0; ks < 4; ks++) {
            if ((ks & 1) == 0) {
                #pragma unroll
                for (int ni = 0; ni < 4; ni++)
                    ldsm4(bhf[ni], st + boff[ni] + (ks >> 1) * 64);
            }
            uint32_t ahf[2][4];
            #pragma unroll
            for (int mi = 0; mi < 2; mi++)
                ldsm4(ahf[mi], st + aoff[mi] + ks * 32);
            #pragma unroll
            for (int mi = 0; mi < 2; mi++)
                #pragma unroll
                for (int ni = 0; ni < 4; ni++)
                    mma16816(acc[mi][ni], ahf[mi], &bhf[ni][2 * (ks & 1)]);
        }

        s = (s + 1) % NSTAGE;
    }

    // ---------------- epilogue ------------------------------------------------------------
    int g = lane >> 2;
    #pragma unroll
    for (int mi = 0; mi < 2; mi++) {
        int row0 = m0 + wm * 32 + mi * 16 + g;
        #pragma unroll
        for (int h = 0; h < 2; h++) {
            int row = row0 + h * 8;
            if (row >= hi) continue;
            if (Ch) {
                #pragma unroll
                for (int ni = 0; ni < 4; ni++) {
                    int cn = n0 + wn * 32 + ni * 8 + tig * 2;
                    float v0 = acc[mi][ni][2 * h + 0] + bias[cn];
                    float v1 = acc[mi][ni][2 * h + 1] + bias[cn + 1];
                    if (do_gelu) { v0 = gelu_tanh(v0); v1 = gelu_tanh(v1); }
                    __half2 hp = __floats2half2_rn(v0, v1);
                    *(uint32_t*)(Ch + (size_t)row * ldc + cn) = *(uint32_t*)&hp;
                }
            } else {
                int tok = rows_token[row];
                float gs = growsc[row];
                float* ob = out_at + (size_t)tok * DMODEL;
                #pragma unroll
                for (int ni = 0; ni < 4; ni++) {
                    int cn = n0 + wn * 32 + ni * 8 + tig * 2;
                    float b0 = (kh == 0) ? bias[cn]     : 0.f;
                    float b1 = (kh == 0) ? bias[cn + 1] : 0.f;
                    atomicAdd(ob + cn,     gs * (acc[mi][ni][2 * h + 0] + b0));
                    atomicAdd(ob + cn + 1, gs * (acc[mi][ni][2 * h + 1] + b1));
                }
            }
        }
    }
}

// ---------------- launcher --------------------------------------------------------------------
extern "C" void kernel_launch(void* const* d_in, const int* in_sizes, int n_in,
                              void* d_out, int out_size)
{
    const float* x   = (const float*)d_in[0];
    const float* wr  = (const float*)d_in[1];
    const float* W1  = (const float*)d_in[2];
    const float* b1  = (const float*)d_in[3];
    const float* W2  = (const float*)d_in[4];
    const float* b2  = (const float*)d_in[5];
    const float* Ws1 = (const float*)d_in[6];
    const float* bs1 = (const float*)d_in[7];
    const float* Ws2 = (const float*)d_in[8];
    const float* bs2 = (const float*)d_in[9];
    float* out = (float*)d_out;

    __half *W1x, *W2x, *xh, *Hh;
    float *b1x, *b2x, *growsc;
    int *offsets, *rows_token;
    cudaGetSymbolAddress((void**)&W1x, d_W1x);
    cudaGetSymbolAddress((void**)&W2x, d_W2x);
    cudaGetSymbolAddress((void**)&b1x, d_b1x);
    cudaGetSymbolAddress((void**)&b2x, d_b2x);
    cudaGetSymbolAddress((void**)&xh, d_xh);
    cudaGetSymbolAddress((void**)&Hh, d_Hh);
    cudaGetSymbolAddress((void**)&growsc, d_growsc);
    cudaGetSymbolAddress((void**)&offsets, d_offsets);
    cudaGetSymbolAddress((void**)&rows_token, d_rows_token);

    cudaFuncSetAttribute(gemm_tc, cudaFuncAttributeMaxDynamicSharedMemorySize, GEMM_SMEM);

    // 1) router + W1/x/bias conversion (fused, overlapped)
    router_cvt<<<NTOK + CVT_BLOCKS, 256>>>(x, wr,
                                           (const float4*)W1, (const float4*)Ws1,
                                           b1, bs1, b2, bs2,
                                           (uint2*)W1x, (uint2*)xh, b1x, b2x);

    // 2) scan + place + gate-scale table
    scanplace_kernel<<<1, 1024>>>();

    // 3) zero output
    cudaMemsetAsync(out, 0, (size_t)NTOK * DMODEL * sizeof(float));

    // 4) up-GEMM (z=0..8) + fused W2 conversion (z=9)
    {
        dim3 g(DFF / 128, 32, NEXPX + 1);
        gemm_tc<<<g, GTHREADS, GEMM_SMEM>>>(xh, DMODEL, rows_token,
                                            W1x, (size_t)DFF * DMODEL, b1x, DFF,
                                            Hh, DFF,
                                            nullptr, nullptr, nullptr,
                                            offsets, DMODEL, 1, 1,
                                            (const float4*)W2, (const float4*)Ws2, (uint2*)W2x,
                                            NEXP * DMODEL * DFF / 4, NEXPX * DMODEL * DFF / 4);
    }

    // 5) down-GEMM, split-K=2, gate-scaled atomic accumulate into out
    {
        dim3 g(DMODEL / 128, 32, NEXPX * 2);
        gemm_tc<<<g, GTHREADS, GEMM_SMEM>>>(Hh, DFF, nullptr,
                                            W2x, (size_t)DMODEL * DFF, b2x, DMODEL,
                                            nullptr, 0,
                                            out, rows_token, growsc,
                                            offsets, DFF, 2, 0,
                                            nullptr, nullptr, nullptr, 0, 0);
    }
}

// round 12
// speedup vs baseline: 1.1921x; 1.1921x over previous
#include <cuda_runtime.h>
#include <cuda_fp16.h>
#include <stdint.h>
#include <math.h>

#define NTOK   4096
#define DMODEL 1024
#define DFF    4096
#define NEXP   8
#define NEXPX  9
#define NASSIGN (NTOK*2)
#define NROWS  (NASSIGN + NTOK)
#define SCALE_F 0.894427190999915878f

// ---------------- device scratch ----------------------------------------------------
__device__ __half d_W1x[(size_t)NEXPX * DFF * DMODEL];
__device__ __half d_W2x[(size_t)NEXPX * DMODEL * DFF];
__device__ float  d_b1x[NEXPX * DFF];
__device__ float  d_b2x[NEXPX * DMODEL];
__device__ __half d_xh[(size_t)NTOK * DMODEL];
__device__ __half d_Hh[(size_t)NROWS * DFF];
__device__ float  d_gates[NASSIGN];
__device__ int    d_assign_e[NASSIGN];
__device__ int    d_offsets[NEXPX + 1];
__device__ int    d_rows_token[NROWS];
__device__ float  d_growsc[NROWS];

// ---------------- helpers --------------------------------------------------------------
__device__ __forceinline__ float gelu_tanh(float v) {
    const float c0 = 0.7978845608028654f;
    const float c1 = 0.044715f;
    float t = tanhf(c0 * (v + c1 * v * v * v));
    return 0.5f * v * (1.0f + t);
}

__device__ __forceinline__ void mma16816(float* c, const uint32_t* a, const uint32_t* b) {
    asm volatile(
        "mma.sync.aligned.m16n8k16.row.col.f32.f16.f16.f32 "
        "{%0,%1,%2,%3}, {%4,%5,%6,%7}, {%8,%9}, {%0,%1,%2,%3};"
        : "+f"(c[0]), "+f"(c[1]), "+f"(c[2]), "+f"(c[3])
        : "r"(a[0]), "r"(a[1]), "r"(a[2]), "r"(a[3]), "r"(b[0]), "r"(b[1]));
}

__device__ __forceinline__ void ldsm4(uint32_t* r, uint32_t addr) {
    asm volatile("ldmatrix.sync.aligned.m8n8.x4.shared.b16 {%0,%1,%2,%3}, [%4];"
                 : "=r"(r[0]), "=r"(r[1]), "=r"(r[2]), "=r"(r[3]) : "r"(addr));
}

__device__ __forceinline__ uint32_t smem_u32(const void* p) {
    uint32_t a;
    asm("{ .reg .u64 t; cvta.to.shared.u64 t, %1; cvt.u32.u64 %0, t; }" : "=r"(a) : "l"(p));
    return a;
}

__device__ __forceinline__ void cp16(uint32_t saddr, const void* g, int srcsz) {
    asm volatile("cp.async.cg.shared.global [%0], [%1], 16, %2;"
                 :: "r"(saddr), "l"(g), "r"(srcsz) : "memory");
}
#define CP_COMMIT() asm volatile("cp.async.commit_group;" ::: "memory")
#define CP_WAIT1()  asm volatile("cp.async.wait_group 1;" ::: "memory")

__device__ __forceinline__ void cvt_store(const float4* __restrict__ src, uint2* __restrict__ dst, int i) {
    float4 v = src[i];
    __half2 a = __floats2half2_rn(v.x, v.y);
    __half2 b = __floats2half2_rn(v.z, v.w);
    dst[i] = make_uint2(*(uint32_t*)&a, *(uint32_t*)&b);
}

// ---------------- launch 1: router + W1/x/bias conversion (fused) -------------------------
#define CVT_BLOCKS 4096
__global__ void router_cvt(const float* __restrict__ x,
                           const float* __restrict__ wr,
                           const float4* __restrict__ W1, const float4* __restrict__ Ws1,
                           const float* __restrict__ b1, const float* __restrict__ bs1,
                           const float* __restrict__ b2, const float* __restrict__ bs2,
                           uint2* __restrict__ W1x, uint2* __restrict__ xh,
                           float* __restrict__ b1x, float* __restrict__ b2x) {
    if (blockIdx.x >= NTOK) {
        int idx0 = (blockIdx.x - NTOK) * blockDim.x + threadIdx.x;
        const int nthr = CVT_BLOCKS * 256;
        const int n4r = NEXP * DFF * DMODEL / 4;
        const int n4t = NEXPX * DFF * DMODEL / 4;
        for (int i = idx0; i < n4t; i += nthr) {
            float4 v = (i < n4r) ? W1[i] : Ws1[i - n4r];
            __half2 a = __floats2half2_rn(v.x, v.y);
            __half2 b = __floats2half2_rn(v.z, v.w);
            W1x[i] = make_uint2(*(uint32_t*)&a, *(uint32_t*)&b);
        }
        for (int i = idx0; i < NTOK * DMODEL / 4; i += nthr)
            cvt_store((const float4*)x, xh, i);
        for (int i = idx0; i < NEXPX * DFF; i += nthr)
            b1x[i] = (i < NEXP * DFF) ? b1[i] : bs1[i - NEXP * DFF];
        for (int i = idx0; i < NEXPX * DMODEL; i += nthr)
            b2x[i] = (i < NEXP * DMODEL) ? b2[i] : bs2[i - NEXP * DMODEL];
        return;
    }
    int t = blockIdx.x;
    int warp = threadIdx.x >> 5;
    int lane = threadIdx.x & 31;
    const float* xr = x + (size_t)t * DMODEL;
    const float* w  = wr + (size_t)warp * DMODEL;
    float s = 0.f;
    #pragma unroll 4
    for (int i = lane; i < DMODEL; i += 32) s += xr[i] * w[i];
    #pragma unroll
    for (int o = 16; o > 0; o >>= 1) s += __shfl_xor_sync(0xFFFFFFFFu, s, o);

    __shared__ float logits[NEXP];
    if (warp < NEXP && lane == 0) logits[warp] = s;
    __syncthreads();

    if (threadIdx.x == 0) {
        float mx = logits[0];
        #pragma unroll
        for (int e = 1; e < NEXP; e++) mx = fmaxf(mx, logits[e]);
        float p[NEXP]; float sum = 0.f;
        #pragma unroll
        for (int e = 0; e < NEXP; e++) { p[e] = expf(logits[e] - mx); sum += p[e]; }
        float inv = 1.f / sum;
        #pragma unroll
        for (int e = 0; e < NEXP; e++) p[e] *= inv;
        int i0 = 0;
        #pragma unroll
        for (int e = 1; e < NEXP; e++) if (p[e] > p[i0]) i0 = e;
        int i1 = -1;
        #pragma unroll
        for (int e = 0; e < NEXP; e++) {
            if (e == i0) continue;
            if (i1 < 0 || p[e] > p[i1]) i1 = e;
        }
        d_gates[2 * t + 0] = p[i0];
        d_gates[2 * t + 1] = p[i1];
        d_assign_e[2 * t + 0] = i0;
        d_assign_e[2 * t + 1] = i1;
    }
}

// ---------------- launch 2: single-block count + scan + place ----------------------------
__global__ void scanplace_kernel() {
    __shared__ int scount[NEXP];
    __shared__ int scursor[NEXP];
    int tid = threadIdx.x;
    if (tid < NEXP) scount[tid] = 0;
    __syncthreads();
    for (int a = tid; a < NASSIGN; a += blockDim.x)
        atomicAdd(&scount[d_assign_e[a]], 1);
    __syncthreads();
    if (tid == 0) {
        int s = 0;
        for (int e = 0; e < NEXP; e++) { d_offsets[e] = s; scursor[e] = s; s += scount[e]; }
        d_offsets[NEXP]  = s;
        d_offsets[NEXPX] = NROWS;
    }
    __syncthreads();
    for (int a = tid; a < NASSIGN; a += blockDim.x) {
        int e = d_assign_e[a];
        int r = atomicAdd(&scursor[e], 1);
        d_rows_token[r] = a >> 1;
        d_growsc[r] = SCALE_F * d_gates[a];
    }
    for (int t = tid; t < NTOK; t += blockDim.x) {
        d_rows_token[NASSIGN + t] = t;
        d_growsc[NASSIGN + t] = SCALE_F;
    }
}

// ================= fp16 HMMA grouped GEMM: 256x128x64, 512 thr, frag-pipelined ===========
// Warp grid 4x4, warp tile 64x32 (best smem-reuse at feasible regs).
// cp.async 3-stage. A-frags double-buffered across ks; B pair-1 loaded after ks=1 mma issue.
#define RS      144
#define T_B     36864             // A: 256 rows x 144B
#define STAGE_B 55296             // + B: 128 rows x 144B
#define NSTAGE  3
#define GEMM_SMEM (NSTAGE * STAGE_B)
#define GTHREADS 512

__global__ __launch_bounds__(GTHREADS, 1)
void gemm_tc(const __half* __restrict__ Ah, int lda, const int* __restrict__ gather,
             const __half* __restrict__ Bh_base, size_t wstride,
             const float* __restrict__ bias_base, size_t bstride,
             __half* __restrict__ Ch, int ldc,
             float* __restrict__ out_at,
             const int* __restrict__ rows_token, const float* __restrict__ growsc,
             const int* __restrict__ offs, int K, int kh_count, int do_gelu,
             const float4* __restrict__ cw8, const float4* __restrict__ cws,
             uint2* __restrict__ cdst, int cn4r, int cn4t)
{
    extern __shared__ char smem[];
    int z = blockIdx.z;
    int nz_gemm = NEXPX * kh_count;
    if (z >= nz_gemm) {
        int idx0 = (blockIdx.y * gridDim.x + blockIdx.x) * blockDim.x + threadIdx.x;
        int nthr = gridDim.x * gridDim.y * blockDim.x;
        for (int i = idx0; i < cn4t; i += nthr) {
            float4 v = (i < cn4r) ? cw8[i] : cws[i - cn4r];
            __half2 a = __floats2half2_rn(v.x, v.y);
            __half2 b = __floats2half2_rn(v.z, v.w);
            cdst[i] = make_uint2(*(uint32_t*)&a, *(uint32_t*)&b);
        }
        return;
    }
    int e  = z / kh_count;
    int kh = z - e * kh_count;
    int Ks = K / kh_count;
    int lo = offs[e];
    int hi = offs[e + 1];
    int m0 = lo + blockIdx.y * 256;
    if (m0 >= hi) return;
    int n0 = blockIdx.x * 128;
    const __half* Bh = Bh_base + (size_t)e * wstride + kh * Ks;
    const float* bias = bias_base + (size_t)e * bstride;

    uint32_t sbase = smem_u32(smem);
    int tid  = threadIdx.x;
    int wid  = tid >> 5;
    int lane = tid & 31;
    int tig  = lane & 3;
    int wm   = wid >> 2;        // 0..3  (M: 4 x 64)
    int wn   = wid & 3;         // 0..3  (N: 4 x 32)

    // ---- cp.async coords: A = 2048 chunks (256 rows x 8), B = 1024 chunks ------------
    const char* pA[4]; int avv[4]; uint32_t sAo[4];
    #pragma unroll
    for (int j = 0; j < 4; j++) {
        int idx = tid + j * GTHREADS;        // 0..2047
        int row = idx >> 3;
        int cb  = (idx & 7) * 16;
        int arow = m0 + row;
        avv[j] = (arow < hi) ? 16 : 0;
        int asrc = (arow < hi) ? (gather ? gather[arow] : arow) : 0;
        pA[j] = (const char*)(Ah + (size_t)asrc * lda + kh * Ks) + cb;
        sAo[j] = sbase + (uint32_t)(row * RS + cb);
    }
    const char* pB[2]; uint32_t sBo[2];
    #pragma unroll
    for (int j = 0; j < 2; j++) {
        int idx = tid + j * GTHREADS;        // 0..1023
        int row = idx >> 3;
        int cb  = (idx & 7) * 16;
        pB[j] = (const char*)(Bh + (size_t)(n0 + row) * K) + cb;
        sBo[j] = sbase + (uint32_t)(T_B + row * RS + cb);
    }

    // ---- ldmatrix lane offsets ----------------------------------------------------------
    uint32_t aoff[4], boff[4];
    #pragma unroll
    for (int mi = 0; mi < 4; mi++)
        aoff[mi] = (uint32_t)((wm * 64 + mi * 16 + (lane & 15)) * RS + (lane >> 4) * 16);
    #pragma unroll
    for (int ni = 0; ni < 4; ni++)
        boff[ni] = (uint32_t)(T_B + (wn * 32 + ni * 8 + (lane & 7)) * RS + (lane >> 3) * 16);

    float acc[4][4][4];
    #pragma unroll
    for (int mi = 0; mi < 4; mi++)
        #pragma unroll
        for (int ni = 0; ni < 4; ni++)
            #pragma unroll
            for (int q = 0; q < 4; q++) acc[mi][ni][q] = 0.f;

    int nk = Ks >> 6;

    auto issue = [&](int kt, int s) {
        uint32_t so = (uint32_t)(s * STAGE_B);
        int kbyte = kt << 7;
        #pragma unroll
        for (int j = 0; j < 4; j++) cp16(sAo[j] + so, pA[j] + kbyte, avv[j]);
        #pragma unroll
        for (int j = 0; j < 2; j++) cp16(sBo[j] + so, pB[j] + kbyte, 16);
        CP_COMMIT();
    };

    issue(0, 0);
    if (nk > 1) issue(1, 1); else CP_COMMIT();

    int s = 0;
    for (int kt = 0; kt < nk; kt++) {
        CP_WAIT1();
        __syncthreads();

        if (kt + 2 < nk) issue(kt + 2, (s + 2) % NSTAGE);
        else CP_COMMIT();

        uint32_t st = sbase + (uint32_t)(s * STAGE_B);

        // fragment-pipelined inner loop over 4 x k16
        uint32_t bhf[4][4];        // B pair (2 ks)
        uint32_t ahf[2][4][4];     // A double buffer
        #pragma unroll
        for (int ni = 0; ni < 4; ni++) ldsm4(bhf[ni], st + boff[ni]);          // B pair0
        #pragma unroll
        for (int mi = 0; mi < 4; mi++) ldsm4(ahf[0][mi], st + aoff[mi]);        // A ks0

        #pragma unroll
        for (int ks = 0; ks < 4; ks++) {
            int cur = ks & 1;
            // issue MMAs for ks (reads ahf[cur], bhf[2*(ks&1)..])
            #pragma unroll
            for (int mi = 0; mi < 4; mi++)
                #pragma unroll
                for (int ni = 0; ni < 4; ni++)
                    mma16816(acc[mi][ni], ahf[cur][mi], &bhf[ni][2 * (ks & 1)]);
            // prefetch next fragments (after mma issue: WAR-safe in program order)
            if (ks == 1) {
                #pragma unroll
                for (int ni = 0; ni < 4; ni++) ldsm4(bhf[ni], st + boff[ni] + 64);  // B pair1
            }
            if (ks < 3) {
                #pragma unroll
                for (int mi = 0; mi < 4; mi++) ldsm4(ahf[cur ^ 1][mi], st + aoff[mi] + (ks + 1) * 32);
            }
        }

        s = (s + 1) % NSTAGE;
    }

    // ---------------- epilogue ------------------------------------------------------------
    int g = lane >> 2;
    #pragma unroll
    for (int mi = 0; mi < 4; mi++) {
        int row0 = m0 + wm * 64 + mi * 16 + g;
        #pragma unroll
        for (int h = 0; h < 2; h++) {
            int row = row0 + h * 8;
            if (row >= hi) continue;
            if (Ch) {
                #pragma unroll
                for (int ni = 0; ni < 4; ni++) {
                    int cn = n0 + wn * 32 + ni * 8 + tig * 2;
                    float v0 = acc[mi][ni][2 * h + 0] + bias[cn];
                    float v1 = acc[mi][ni][2 * h + 1] + bias[cn + 1];
                    if (do_gelu) { v0 = gelu_tanh(v0); v1 = gelu_tanh(v1); }
                    __half2 hp = __floats2half2_rn(v0, v1);
                    *(uint32_t*)(Ch + (size_t)row * ldc + cn) = *(uint32_t*)&hp;
                }
            } else {
                int tok = rows_token[row];
                float gs = growsc[row];
                float* ob = out_at + (size_t)tok * DMODEL;
                #pragma unroll
                for (int ni = 0; ni < 4; ni++) {
                    int cn = n0 + wn * 32 + ni * 8 + tig * 2;
                    float b0 = (kh == 0) ? bias[cn]     : 0.f;
                    float b1 = (kh == 0) ? bias[cn + 1] : 0.f;
                    atomicAdd(ob + cn,     gs * (acc[mi][ni][2 * h + 0] + b0));
                    atomicAdd(ob + cn + 1, gs * (acc[mi][ni][2 * h + 1] + b1));
                }
            }
        }
    }
}

// ---------------- launcher --------------------------------------------------------------------
extern "C" void kernel_launch(void* const* d_in, const int* in_sizes, int n_in,
                              void* d_out, int out_size)
{
    const float* x   = (const float*)d_in[0];
    const float* wr  = (const float*)d_in[1];
    const float* W1  = (const float*)d_in[2];
    const float* b1  = (const float*)d_in[3];
    const float* W2  = (const float*)d_in[4];
    const float* b2  = (const float*)d_in[5];
    const float* Ws1 = (const float*)d_in[6];
    const float* bs1 = (const float*)d_in[7];
    const float* Ws2 = (const float*)d_in[8];
    const float* bs2 = (const float*)d_in[9];
    float* out = (float*)d_out;

    __half *W1x, *W2x, *xh, *Hh;
    float *b1x, *b2x, *growsc;
    int *offsets, *rows_token;
    cudaGetSymbolAddress((void**)&W1x, d_W1x);
    cudaGetSymbolAddress((void**)&W2x, d_W2x);
    cudaGetSymbolAddress((void**)&b1x, d_b1x);
    cudaGetSymbolAddress((void**)&b2x, d_b2x);
    cudaGetSymbolAddress((void**)&xh, d_xh);
    cudaGetSymbolAddress((void**)&Hh, d_Hh);
    cudaGetSymbolAddress((void**)&growsc, d_growsc);
    cudaGetSymbolAddress((void**)&offsets, d_offsets);
    cudaGetSymbolAddress((void**)&rows_token, d_rows_token);

    cudaFuncSetAttribute(gemm_tc, cudaFuncAttributeMaxDynamicSharedMemorySize, GEMM_SMEM);

    // 1) router + W1/x/bias conversion (fused, overlapped)
    router_cvt<<<NTOK + CVT_BLOCKS, 256>>>(x, wr,
                                           (const float4*)W1, (const float4*)Ws1,
                                           b1, bs1, b2, bs2,
                                           (uint2*)W1x, (uint2*)xh, b1x, b2x);

    // 2) scan + place + gate-scale table
    scanplace_kernel<<<1, 1024>>>();

    // 3) zero output
    cudaMemsetAsync(out, 0, (size_t)NTOK * DMODEL * sizeof(float));

    // 4) up-GEMM (z=0..8) + fused W2 conversion (z=9)
    {
        dim3 g(DFF / 128, 16, NEXPX + 1);
        gemm_tc<<<g, GTHREADS, GEMM_SMEM>>>(xh, DMODEL, rows_token,
                                            W1x, (size_t)DFF * DMODEL, b1x, DFF,
                                            Hh, DFF,
                                            nullptr, nullptr, nullptr,
                                            offsets, DMODEL, 1, 1,
                                            (const float4*)W2, (const float4*)Ws2, (uint2*)W2x,
                                            NEXP * DMODEL * DFF / 4, NEXPX * DMODEL * DFF / 4);
    }

    // 5) down-GEMM, split-K=2, gate-scaled atomic accumulate into out
    {
        dim3 g(DMODEL / 128, 16, NEXPX * 2);
        gemm_tc<<<g, GTHREADS, GEMM_SMEM>>>(Hh, DFF, nullptr,
                                            W2x, (size_t)DMODEL * DFF, b2x, DMODEL,
                                            nullptr, 0,
                                            out, rows_token, growsc,
                                            offsets, DFF, 2, 0,
                                            nullptr, nullptr, nullptr, 0, 0);
    }
}